// round 17
// baseline (speedup 1.0000x reference)
#include <cuda_runtime.h>
#include <cuda_bf16.h>
#include <math.h>
#include <stddef.h>
#include <stdint.h>

// ---------------- problem constants ----------------
#define VSZ   4000
#define ESZ   256
#define HSZ   256
#define MSZ   128
#define BSZ   32
#define LSEG  4
#define SSEG  126            // M-2
#define SB    (SSEG*BSZ)     // 4032
#define G4    (4*HSZ)        // 1024
#define NROWS ((LSEG+1)*SB)  // 20160
#define MTILES 158           // ceil(20160/128)
#define NROWS_PAD (MTILES*128)
#define VPAD  4096
#define NCHUNK 32
#define NEGINF (-1.0e6f)

// ---------------- scratch ----------------
__device__ float g_issing [MSZ*BSZ];
__device__ float g_enc_xg [MSZ*BSZ*G4];
__device__ float g_sos    [4096*HSZ];
__device__ float g_dxg0   [4096*G4];
__device__ float g_vxg    [VPAD*G4];
__device__ float g_gates  [4096*G4];
__device__ float g_dec_h  [4096*HSZ];
__device__ float g_dec_c  [SB*HSZ];
__device__ int   g_flags  [BSZ*MSZ];             // per (b,t) arrival counters
__device__ float g_hbuf   [2*BSZ*HSZ];           // double-buffered encoder h
__device__ __nv_bfloat16 g_ibf  [MSZ*BSZ*ESZ];
__device__ __nv_bfloat16 g_eobf [MSZ*BSZ*ESZ];
__device__ __nv_bfloat16 g_sosbf[4096*ESZ];
__device__ __nv_bfloat16 g_dhbf [4096*ESZ];
__device__ __nv_bfloat16 g_abf[NROWS_PAD*ESZ];
__device__ __nv_bfloat16 g_bbf[VPAD*ESZ];
__device__ __nv_bfloat16 g_wihe[G4*ESZ];
__device__ __nv_bfloat16 g_whhe[G4*ESZ];
__device__ __nv_bfloat16 g_wihd[G4*ESZ];
__device__ __nv_bfloat16 g_whhd[G4*ESZ];
__device__ __nv_bfloat16 g_sosw[HSZ*ESZ];
__device__ __nv_bfloat16 g_dhtw[HSZ*ESZ];
__device__ float g_lse    [NROWS];
__device__ float g_tgtlog [NROWS];
__device__ float g_eoslog [NROWS];
__device__ float g_logpy  [(SSEG+1)*LSEG*BSZ];

__device__ __forceinline__ float sigmoidf(float x) { return 1.0f/(1.0f+__expf(-x)); }

// ================= mma.sync / ldmatrix / cp.async helpers ===
__device__ __forceinline__ uint32_t smem_u32(const void* p) {
    return (uint32_t)__cvta_generic_to_shared(p);
}
__device__ __forceinline__ void cp16(uint32_t dst, const void* src) {
    asm volatile("cp.async.cg.shared.global [%0], [%1], 16;" :: "r"(dst), "l"(src));
}
#define CP_COMMIT() asm volatile("cp.async.commit_group;" ::: "memory")
#define CP_WAIT1()  asm volatile("cp.async.wait_group 1;"  ::: "memory")
#define CP_WAIT0()  asm volatile("cp.async.wait_group 0;"  ::: "memory")

__device__ __forceinline__ void ldsm4(uint32_t& r0, uint32_t& r1, uint32_t& r2,
                                      uint32_t& r3, uint32_t addr) {
    asm volatile("ldmatrix.sync.aligned.m8n8.x4.shared.b16 {%0,%1,%2,%3}, [%4];"
                 : "=r"(r0), "=r"(r1), "=r"(r2), "=r"(r3) : "r"(addr));
}
__device__ __forceinline__ void mma16816(float* d, uint32_t a0, uint32_t a1,
                                         uint32_t a2, uint32_t a3,
                                         uint32_t b0, uint32_t b1) {
    asm volatile("mma.sync.aligned.m16n8k16.row.col.f32.bf16.bf16.f32 "
        "{%0,%1,%2,%3}, {%4,%5,%6,%7}, {%8,%9}, {%0,%1,%2,%3};"
        : "+f"(d[0]), "+f"(d[1]), "+f"(d[2]), "+f"(d[3])
        : "r"(a0), "r"(a1), "r"(a2), "r"(a3), "r"(b0), "r"(b1));
}

// Load a 128-row x 256-col bf16 tile (512B rows) gmem->smem with XOR-swizzle.
__device__ __forceinline__ void load_tile_async(uint32_t smbase,
                                                const __nv_bfloat16* g, int tid) {
#pragma unroll
    for (int l = 0; l < 16; l++) {
        int u = tid + l*256;
        int row = u >> 5, c = u & 31;
        uint32_t dst = smbase + row*512 + ((c ^ (row & 7)) << 4);
        cp16(dst, (const char*)g + (size_t)row*512 + c*16);
    }
}

// ---------------- prep: embed (bf16) + is_single + emb->bf16 (fused) ----------------
__global__ void prep_kernel(const int* __restrict__ x, const float* __restrict__ emb,
                            __nv_bfloat16* __restrict__ ibf, float* __restrict__ issing,
                            __nv_bfloat16* __restrict__ bbf)
{
    int row = blockIdx.x, c = threadIdx.x;   // grid 4096 = MSZ*BSZ = VPAD
    int t = row >> 5, b = row & 31;
    int tok = x[b*MSZ + t];
    ibf[(size_t)row*ESZ + c] = __float2bfloat16(emb[(size_t)tok*ESZ + c]);
    if (c == 0)
        issing[row] = (tok == 0 || tok == 1 || tok == 2) ? NEGINF : 0.0f;
    bbf[(size_t)row*ESZ + c] = (row < VSZ) ? __float2bfloat16(emb[(size_t)row*ESZ + c])
                                           : __float2bfloat16(0.0f);
}

// ---------------- all weight converts + encoder flag reset (fused) ----------------
__global__ void cvt_wall(const float* __restrict__ s1, const float* __restrict__ s2,
                         const float* __restrict__ s3, const float* __restrict__ s4,
                         const float* __restrict__ s5, const float* __restrict__ s6,
                         __nv_bfloat16* __restrict__ d1, __nv_bfloat16* __restrict__ d2,
                         __nv_bfloat16* __restrict__ d3, __nv_bfloat16* __restrict__ d4,
                         __nv_bfloat16* __restrict__ d5, __nv_bfloat16* __restrict__ d6,
                         int* __restrict__ flags)
{
    int i = blockIdx.x*256 + threadIdx.x;    // grid 1024 -> i < 262144 = G4*ESZ
    d1[i] = __float2bfloat16(s1[i]);
    d2[i] = __float2bfloat16(s2[i]);
    d3[i] = __float2bfloat16(s3[i]);
    d4[i] = __float2bfloat16(s4[i]);
    if (i < HSZ*ESZ) { d5[i] = __float2bfloat16(s5[i]); d6[i] = __float2bfloat16(s6[i]); }
    if (i < BSZ*MSZ) flags[i] = 0;
}

// ================ generic bf16 tensor-core GEMM: C = A @ W^T (+bias)[tanh] ===
#define GM_SMA 0
#define GM_SMW 65536
#define GM_TOT 131072

__global__ __launch_bounds__(256, 1)
void gemm_mma(const __nv_bfloat16* __restrict__ A, const __nv_bfloat16* __restrict__ W,
              const float* __restrict__ b1, const float* __restrict__ b2,
              float* __restrict__ C, __nv_bfloat16* __restrict__ Cbf,
              int R, int N, int epi)
{
    extern __shared__ char sm[];
    uint32_t smb = smem_u32(sm);
    int tid = threadIdx.x, wid = tid >> 5, lane = tid & 31;
    int band = wid & 3, half = wid >> 2;
    int m0 = blockIdx.x * 128, n0 = blockIdx.y * 128;

    load_tile_async(smb + GM_SMA, A + (size_t)m0*ESZ, tid);
    load_tile_async(smb + GM_SMW, W + (size_t)n0*ESZ, tid);
    CP_COMMIT();

    int swz = lane & 7;
    uint32_t aBase[2];
#pragma unroll
    for (int mi = 0; mi < 2; mi++)
        aBase[mi] = smb + GM_SMA + (uint32_t)(band*32 + mi*16 + (lane & 15))*512;
    int hiA = lane >> 4;
    int hiB = (lane >> 3) & 1;
    uint32_t bRow[4];
#pragma unroll
    for (int p = 0; p < 4; p++)
        bRow[p] = smb + GM_SMW + (uint32_t)(half*64 + p*16 + ((lane >> 4) & 1)*8 + (lane & 7))*512;

    float acc[2][8][4];
#pragma unroll
    for (int mi = 0; mi < 2; mi++)
#pragma unroll
        for (int ni = 0; ni < 8; ni++)
#pragma unroll
            for (int k = 0; k < 4; k++) acc[mi][ni][k] = 0.0f;

    CP_WAIT0();
    __syncthreads();

#pragma unroll
    for (int kb = 0; kb < 16; kb++) {
        uint32_t a[2][4];
#pragma unroll
        for (int mi = 0; mi < 2; mi++) {
            uint32_t addr = aBase[mi] + (uint32_t)(((2*kb + hiA) ^ swz) << 4);
            ldsm4(a[mi][0], a[mi][1], a[mi][2], a[mi][3], addr);
        }
#pragma unroll
        for (int p = 0; p < 4; p++) {
            uint32_t b0, b1r, b2r, b3;
            uint32_t addr = bRow[p] + (uint32_t)(((2*kb + hiB) ^ swz) << 4);
            ldsm4(b0, b1r, b2r, b3, addr);
#pragma unroll
            for (int mi = 0; mi < 2; mi++) {
                mma16816(acc[mi][2*p    ], a[mi][0], a[mi][1], a[mi][2], a[mi][3], b0, b1r);
                mma16816(acc[mi][2*p + 1], a[mi][0], a[mi][1], a[mi][2], a[mi][3], b2r, b3);
            }
        }
    }

    // epilogue
#pragma unroll
    for (int mi = 0; mi < 2; mi++) {
#pragma unroll
        for (int hi = 0; hi < 2; hi++) {
            int row = m0 + band*32 + mi*16 + hi*8 + (lane >> 2);
            if (row >= R) continue;
#pragma unroll
            for (int ni = 0; ni < 8; ni++) {
#pragma unroll
                for (int j = 0; j < 2; j++) {
                    int col = n0 + half*64 + ni*8 + (lane & 3)*2 + j;
                    float v = acc[mi][ni][hi*2 + j];
                    if (epi != 2) { v += b1[col]; if (b2) v += b2[col]; }
                    if (epi == 1) v = tanhf(v);
                    C[(size_t)row*N + col] = v;
                    if (Cbf) Cbf[(size_t)row*N + col] = __float2bfloat16(v);
                }
            }
        }
    }
}

// ---------------- encoder: 4 CTAs per batch element, L1-resident weights ----------------
__device__ __forceinline__ void fma2bf(float& acc, uint32_t u, float hlo, float hhi) {
    acc = fmaf(__uint_as_float(u << 16), hlo, acc);
    acc = fmaf(__uint_as_float(u & 0xffff0000u), hhi, acc);
}

__global__ __launch_bounds__(256)
void enc_lstm(const float* __restrict__ xg, const __nv_bfloat16* __restrict__ whhbf,
              const float* __restrict__ h0, const float* __restrict__ c0,
              __nv_bfloat16* __restrict__ eobf, int* __restrict__ flags,
              float* __restrict__ hbuf)
{
    int blk = blockIdx.x;
    int b = blk >> 2, q = blk & 3;        // 4 blocks per batch element
    int tid = threadIdx.x;
    int g = tid >> 6, jj = tid & 63;
    int grow = g*256 + q*64 + jj;         // this thread's gate row in [0,1024)
    __shared__ float hsh[HSZ];
    __shared__ float gsh[4][64];

    hsh[tid] = h0[tid];
    float c = (tid < 64) ? c0[q*64 + tid] : 0.0f;
    const uint4* wrow = (const uint4*)(whhbf + (size_t)grow*HSZ);
    __syncthreads();

    float accn = xg[((size_t)0*BSZ + b)*G4 + grow];   // prefetched step-0 gate
    for (int t = 0; t < MSZ; t++) {
        float acc = accn;
        if (t + 1 < MSZ)                              // prefetch next step early;
            accn = xg[((size_t)(t+1)*BSZ + b)*G4 + grow];  // latency hides under FMAs
#pragma unroll 8
        for (int kk = 0; kk < 32; kk++) {
            uint4 w = wrow[kk];
            float4 ha = *(const float4*)&hsh[kk*8];
            float4 hb = *(const float4*)&hsh[kk*8 + 4];
            fma2bf(acc, w.x, ha.x, ha.y);
            fma2bf(acc, w.y, ha.z, ha.w);
            fma2bf(acc, w.z, hb.x, hb.y);
            fma2bf(acc, w.w, hb.z, hb.w);
        }
        gsh[g][jj] = acc;
        __syncthreads();
        if (tid < 64) {
            int j2 = q*64 + tid;
            float gi = gsh[0][tid], gf = gsh[1][tid], gv = gsh[2][tid], go = gsh[3][tid];
            float cn = sigmoidf(gf)*c + sigmoidf(gi)*tanhf(gv);
            float hn = sigmoidf(go)*tanhf(cn);
            c = cn;
            asm volatile("st.global.cg.f32 [%0], %1;"
                :: "l"(hbuf + ((size_t)(t & 1)*BSZ + b)*HSZ + j2), "f"(hn) : "memory");
            eobf[((size_t)t*BSZ + b)*HSZ + j2] = __float2bfloat16(0.5f*hn);
        }
        __threadfence();
        __syncthreads();
        if (tid == 0) atomicAdd(&flags[b*MSZ + t], 1);
        if (t < MSZ-1) {
            if (tid == 0) {
                while (((volatile int*)flags)[b*MSZ + t] < 4) {}
            }
            __syncthreads();
            __threadfence();
            if (tid < 64) {
                float4 hv;
                const float* src = hbuf + ((size_t)(t & 1)*BSZ + b)*HSZ + tid*4;
                asm volatile("ld.global.cg.v4.f32 {%0,%1,%2,%3}, [%4];"
                    : "=f"(hv.x), "=f"(hv.y), "=f"(hv.z), "=f"(hv.w) : "l"(src));
                *(float4*)&hsh[tid*4] = hv;
            }
            __syncthreads();
        }
    }
}

// ---------------- decoder pointwise: 4 rows per block, 1024 threads ----------------
__global__ __launch_bounds__(1024)
void dec_point(const float* __restrict__ gates, const float* __restrict__ xg0,
               const float* __restrict__ vxg, const int* __restrict__ x,
               const float* __restrict__ bih, const float* __restrict__ bhh,
               float* __restrict__ cc, __nv_bfloat16* __restrict__ hbf,
               __nv_bfloat16* __restrict__ abf, int t)
{
    int r = blockIdx.x*4 + (threadIdx.x >> 8);
    int j = threadIdx.x & 255;
    int s = r >> 5, b = r & 31;
    const float* base = nullptr;
    if (t == 0) base = xg0 + (size_t)r*G4;
    else {
        int pos = s + t;
        if (pos <= MSZ-1) base = vxg + (size_t)x[b*MSZ + pos]*G4;
    }
    float xi, xf, xgv, xo;
    if (base) { xi = base[j]; xf = base[j+256]; xgv = base[j+512]; xo = base[j+768]; }
    else {     xi = bih[j]+bhh[j]; xf = bih[j+256]+bhh[j+256];
               xgv = bih[j+512]+bhh[j+512]; xo = bih[j+768]+bhh[j+768]; }
    const float* gr = gates + (size_t)r*G4;
    float gi = gr[j] + xi, gf = gr[j+256] + xf, gg = gr[j+512] + xgv, go = gr[j+768] + xo;
    float cp = (t == 0) ? 0.0f : cc[(size_t)r*HSZ + j];
    float cn = sigmoidf(gf)*cp + sigmoidf(gi)*tanhf(gg);
    float hn = sigmoidf(go)*tanhf(cn);
    cc[(size_t)r*HSZ + j] = cn;
    __nv_bfloat16 hb = __float2bfloat16(hn);
    hbf[(size_t)r*HSZ + j] = hb;
    abf[((size_t)t*SB + r)*ESZ + j] = hb;
}

// ================ bf16 mma.sync logits + fused online LSE (full vocab sweep) ===
#define SMA    0
#define SMB0   65536
#define SMB1   131072
#define SMBIAS 196608
#define SMRED  212992
#define SMTOT  214016

__global__ __launch_bounds__(256, 1)
void logits_mma(const __nv_bfloat16* __restrict__ abf, const __nv_bfloat16* __restrict__ bbf,
                const float* __restrict__ e2vb, const int* __restrict__ x,
                float* __restrict__ lse, float* __restrict__ tgtlog,
                float* __restrict__ eoslog)
{
    extern __shared__ char sm[];
    uint32_t smb = smem_u32(sm);
    int tid = threadIdx.x, wid = tid >> 5, lane = tid & 31;
    int band = wid & 3, half = wid >> 2;
    int m0 = blockIdx.x * 128;

    load_tile_async(smb + SMA, abf + (size_t)m0*ESZ, tid);
    CP_COMMIT();
    load_tile_async(smb + SMB0, bbf, tid);
    CP_COMMIT();
    load_tile_async(smb + SMB1, bbf + (size_t)128*ESZ, tid);
    CP_COMMIT();
    float* bias_s = (float*)(sm + SMBIAS);
#pragma unroll
    for (int l = 0; l < 16; l++) {
        int i = tid + l*256;
        bias_s[i] = (i < VSZ) ? e2vb[i] : 0.0f;
    }

    int vt[4];
    float Mv[4], Sv[4];
#pragma unroll
    for (int sl = 0; sl < 4; sl++) {
        int rl = band*32 + (sl >> 1)*16 + (sl & 1)*8 + (lane >> 2);
        int row = m0 + rl;
        vt[sl] = -1;
        if (row < NROWS) {
            int t = row / SB; int rr = row % SB; int s = rr >> 5; int b = rr & 31;
            if (t < LSEG) { int pos = s + 1 + t; vt[sl] = (pos <= MSZ-1) ? x[b*MSZ + pos] : 0; }
        }
        Mv[sl] = -3.0e38f; Sv[sl] = 0.0f;
    }

    int swz = lane & 7;
    uint32_t aBase[2];
#pragma unroll
    for (int mi = 0; mi < 2; mi++)
        aBase[mi] = smb + SMA + (uint32_t)(band*32 + mi*16 + (lane & 15))*512;
    int hiA = lane >> 4;
    int hiB = (lane >> 3) & 1;
    uint32_t bRow[4];
#pragma unroll
    for (int p = 0; p < 4; p++)
        bRow[p] = (uint32_t)(half*64 + p*16 + ((lane >> 4) & 1)*8 + (lane & 7))*512;

    CP_WAIT1();
    __syncthreads();

    for (int c = 0; c < NCHUNK; c++) {
        uint32_t bbase = smb + ((c & 1) ? SMB1 : SMB0);
        float acc[2][8][4];
#pragma unroll
        for (int mi = 0; mi < 2; mi++)
#pragma unroll
            for (int ni = 0; ni < 8; ni++)
#pragma unroll
                for (int k = 0; k < 4; k++) acc[mi][ni][k] = 0.0f;

#pragma unroll
        for (int kb = 0; kb < 16; kb++) {
            uint32_t a[2][4];
#pragma unroll
            for (int mi = 0; mi < 2; mi++) {
                uint32_t addr = aBase[mi] + (uint32_t)(((2*kb + hiA) ^ swz) << 4);
                ldsm4(a[mi][0], a[mi][1], a[mi][2], a[mi][3], addr);
            }
#pragma unroll
            for (int p = 0; p < 4; p++) {
                uint32_t b0, b1, b2, b3;
                uint32_t addr = bbase + bRow[p] + (uint32_t)(((2*kb + hiB) ^ swz) << 4);
                ldsm4(b0, b1, b2, b3, addr);
#pragma unroll
                for (int mi = 0; mi < 2; mi++) {
                    mma16816(acc[mi][2*p    ], a[mi][0], a[mi][1], a[mi][2], a[mi][3], b0, b1);
                    mma16816(acc[mi][2*p + 1], a[mi][0], a[mi][1], a[mi][2], a[mi][3], b2, b3);
                }
            }
        }

        int vb = c*128 + half*64 + (lane & 3)*2;
#pragma unroll
        for (int sl = 0; sl < 4; sl++) {
            int mi = sl >> 1, hi = sl & 1;
            int rowg = m0 + band*32 + mi*16 + hi*8 + (lane >> 2);
            float gm = -3.0e38f;
            float lv[16];
#pragma unroll
            for (int ni = 0; ni < 8; ni++) {
#pragma unroll
                for (int j = 0; j < 2; j++) {
                    int v = vb + ni*8 + j;
                    float val = acc[mi][ni][hi*2 + j] + bias_s[v];
                    if (v == vt[sl]) tgtlog[rowg] = val;
                    if (v == 3 && rowg < NROWS) eoslog[rowg] = val;
                    float e = (v < VSZ) ? val : -1.0e30f;
                    lv[ni*2 + j] = e;
                    gm = fmaxf(gm, e);
                }
            }
            float gs = 0.0f;
#pragma unroll
            for (int q = 0; q < 16; q++) gs += __expf(lv[q] - gm);
#pragma unroll
            for (int d = 1; d <= 2; d <<= 1) {
                float m2 = __shfl_xor_sync(0xffffffffu, gm, d);
                float s2 = __shfl_xor_sync(0xffffffffu, gs, d);
                float nm = fmaxf(gm, m2);
                gs = gs*__expf(gm - nm) + s2*__expf(m2 - nm);
                gm = nm;
            }
            float nm = fmaxf(Mv[sl], gm);
            Sv[sl] = Sv[sl]*__expf(Mv[sl] - nm) + gs*__expf(gm - nm);
            Mv[sl] = nm;
        }

        __syncthreads();
        if (c + 2 < NCHUNK)
            load_tile_async(smb + ((c & 1) ? SMB1 : SMB0),
                            bbf + (size_t)(c + 2)*128*ESZ, tid);
        CP_COMMIT();
        CP_WAIT1();
        __syncthreads();
    }

    float* smm = (float*)(sm + SMRED);
    float* sms = smm + 128;
    if (half == 0 && (lane & 3) == 0) {
#pragma unroll
        for (int sl = 0; sl < 4; sl++) {
            int rl = band*32 + (sl >> 1)*16 + (sl & 1)*8 + (lane >> 2);
            smm[rl] = Mv[sl]; sms[rl] = Sv[sl];
        }
    }
    __syncthreads();
    if (half == 1 && (lane & 3) == 0) {
#pragma unroll
        for (int sl = 0; sl < 4; sl++) {
            int rl = band*32 + (sl >> 1)*16 + (sl & 1)*8 + (lane >> 2);
            float m2 = smm[rl], s2 = sms[rl];
            float nm = fmaxf(Mv[sl], m2);
            float s = Sv[sl]*__expf(Mv[sl] - nm) + s2*__expf(m2 - nm);
            int rowg = m0 + rl;
            if (rowg < NROWS) lse[rowg] = nm + __logf(s);
        }
    }
}

// ---------------- segment log-probs -> logpy table ----------------
__global__ void logpy_kernel(const float* __restrict__ lse, const float* __restrict__ tgtlog,
                             const float* __restrict__ eoslog, const float* __restrict__ issing,
                             float* __restrict__ logpy)
{
    int idx = blockIdx.x*blockDim.x + threadIdx.x;
    if (idx >= (SSEG+1)*BSZ) return;
    int e = idx >> 5, b = idx & 31;
    if (e == 0) {
        logpy[b] = 0.0f;
        for (int k = 1; k < LSEG; k++) logpy[k*BSZ + b] = NEGINF;
        return;
    }
    int s = e - 1;
    int r = s*BSZ + b;
    float cum = 0.0f;
    float is_start = issing[(s+1)*BSZ + b];
    int jlen = SSEG - s; if (jlen > LSEG) jlen = LSEG;
    for (int k = 0; k < LSEG; k++) {
        int rowk = k*SB + r;
        float tlp = tgtlog[rowk] - lse[rowk];
        float segis = ((s+1+k) <= MSZ-1) ? issing[(s+1+k)*BSZ + b] : 0.0f;
        cum += tlp + ((k >= 1) ? segis : 0.0f);
        int rowe = (k+1)*SB + r;
        float eos = eoslog[rowe] - lse[rowe];
        float val = cum + ((k >= 1) ? is_start : 0.0f) + eos;
        if (k >= jlen) val = NEGINF;
        logpy[(e*LSEG + k)*BSZ + b] = val;
    }
}

// ---------------- final DP over segmentations ----------------
__global__ void dp_kernel(const float* __restrict__ logpy, const int* __restrict__ lengths,
                          float* __restrict__ out)
{
    int b = threadIdx.x;
    __shared__ float alph[MSZ-1][BSZ];
    float buf[LSEG] = {0.0f, NEGINF, NEGINF, NEGINF};
    alph[0][b] = 0.0f;
    for (int m = 1; m < MSZ-1; m++) {
        float v[LSEG], mx = -3.0e38f;
#pragma unroll
        for (int k = 0; k < LSEG; k++) {
            int e = m - k;
            float slp = (e >= 1) ? logpy[(e*LSEG + k)*BSZ + b] : NEGINF;
            v[k] = buf[k] + slp;
            mx = fmaxf(mx, v[k]);
        }
        float ssum = 0.0f;
#pragma unroll
        for (int k = 0; k < LSEG; k++) ssum += __expf(v[k]-mx);
        float a = mx + __logf(ssum);
        buf[3] = buf[2]; buf[2] = buf[1]; buf[1] = buf[0]; buf[0] = a;
        alph[m][b] = a;
    }
    int Lb = lengths[b];
    float nll = -alph[Lb-2][b];
    float tlen = (float)Lb;
#pragma unroll
    for (int off = 16; off; off >>= 1) {
        nll  += __shfl_down_sync(0xffffffffu, nll,  off);
        tlen += __shfl_down_sync(0xffffffffu, tlen, off);
    }
    if (b == 0) out[0] = nll / (tlen - 2.0f*BSZ);
}

// ---------------- launch ----------------
extern "C" void kernel_launch(void* const* d_in, const int* in_sizes, int n_in,
                              void* d_out, int out_size)
{
    const int*   x        = (const int*)  d_in[0];
    const int*   lengths  = (const int*)  d_in[1];
    const float* emb      = (const float*)d_in[2];
    const float* e2vb     = (const float*)d_in[3];
    const float* enc_Wih  = (const float*)d_in[4];
    const float* enc_Whh  = (const float*)d_in[5];
    const float* enc_bih  = (const float*)d_in[6];
    const float* enc_bhh  = (const float*)d_in[7];
    const float* enc_h0   = (const float*)d_in[8];
    const float* enc_c0   = (const float*)d_in[9];
    const float* dec_Wih  = (const float*)d_in[10];
    const float* dec_Whh  = (const float*)d_in[11];
    const float* dec_bih  = (const float*)d_in[12];
    const float* dec_bhh  = (const float*)d_in[13];
    const float* dht_W    = (const float*)d_in[14];
    const float* dht_b    = (const float*)d_in[15];
    const float* sos_W    = (const float*)d_in[16];
    const float* sos_b    = (const float*)d_in[17];
    float* out = (float*)d_out;

    float *p_issing, *p_enc_xg, *p_sos, *p_dxg0, *p_vxg, *p_gates, *p_dec_h, *p_dec_c;
    float *p_lse, *p_tgt, *p_eos, *p_logpy, *p_hbuf;
    int *p_flags;
    __nv_bfloat16 *p_ibf, *p_eobf, *p_sosbf, *p_dhbf, *p_abf, *p_bbf;
    __nv_bfloat16 *p_wihe, *p_whhe, *p_wihd, *p_whhd, *p_sosw, *p_dhtw;
    cudaGetSymbolAddress((void**)&p_issing,  g_issing);
    cudaGetSymbolAddress((void**)&p_enc_xg,  g_enc_xg);
    cudaGetSymbolAddress((void**)&p_sos,     g_sos);
    cudaGetSymbolAddress((void**)&p_dxg0,    g_dxg0);
    cudaGetSymbolAddress((void**)&p_vxg,     g_vxg);
    cudaGetSymbolAddress((void**)&p_gates,   g_gates);
    cudaGetSymbolAddress((void**)&p_dec_h,   g_dec_h);
    cudaGetSymbolAddress((void**)&p_dec_c,   g_dec_c);
    cudaGetSymbolAddress((void**)&p_flags,   g_flags);
    cudaGetSymbolAddress((void**)&p_hbuf,    g_hbuf);
    cudaGetSymbolAddress((void**)&p_ibf,     g_ibf);
    cudaGetSymbolAddress((void**)&p_eobf,    g_eobf);
    cudaGetSymbolAddress((void**)&p_sosbf,   g_sosbf);
    cudaGetSymbolAddress((void**)&p_dhbf,    g_dhbf);
    cudaGetSymbolAddress((void**)&p_abf,     g_abf);
    cudaGetSymbolAddress((void**)&p_bbf,     g_bbf);
    cudaGetSymbolAddress((void**)&p_wihe,    g_wihe);
    cudaGetSymbolAddress((void**)&p_whhe,    g_whhe);
    cudaGetSymbolAddress((void**)&p_wihd,    g_wihd);
    cudaGetSymbolAddress((void**)&p_whhd,    g_whhd);
    cudaGetSymbolAddress((void**)&p_sosw,    g_sosw);
    cudaGetSymbolAddress((void**)&p_dhtw,    g_dhtw);
    cudaGetSymbolAddress((void**)&p_lse,     g_lse);
    cudaGetSymbolAddress((void**)&p_tgt,     g_tgtlog);
    cudaGetSymbolAddress((void**)&p_eos,     g_eoslog);
    cudaGetSymbolAddress((void**)&p_logpy,   g_logpy);

    cudaFuncSetAttribute(logits_mma, cudaFuncAttributeMaxDynamicSharedMemorySize, SMTOT);
    cudaFuncSetAttribute(gemm_mma,   cudaFuncAttributeMaxDynamicSharedMemorySize, GM_TOT);

    // 1. prep: embed (bf16) + is_single + emb->bf16
    prep_kernel<<<VPAD, 256>>>(x, emb, p_ibf, p_issing, p_bbf);
    // 2. all weight converts + flag reset
    cvt_wall<<<(G4*ESZ)/256, 256>>>(enc_Wih, enc_Whh, dec_Wih, dec_Whh, sos_W, dht_W,
                                    p_wihe, p_whhe, p_wihd, p_whhd, p_sosw, p_dhtw,
                                    p_flags);
    // 3. encoder input gates (tensor core)
    gemm_mma<<<dim3(32, 8), 256, GM_TOT>>>(p_ibf, p_wihe, enc_bih, enc_bhh,
                                           p_enc_xg, nullptr, MSZ*BSZ, G4, 0);
    // 4. encoder recurrence  <-- ncu's captured launch
    enc_lstm<<<BSZ*4, 256>>>(p_enc_xg, p_whhe, enc_h0, enc_c0, p_eobf,
                             p_flags, p_hbuf);
    // 5. sos (bf16 out for dxg0)
    gemm_mma<<<dim3(32, 2), 256, GM_TOT>>>(p_eobf, p_sosw, sos_b, nullptr,
                                           p_sos, p_sosbf, SB, HSZ, 0);
    // 6. dec_h0 = tanh(...) (bf16 out)
    gemm_mma<<<dim3(32, 2), 256, GM_TOT>>>(p_eobf, p_dhtw, dht_b, nullptr,
                                           p_dec_h, p_dhbf, SB, HSZ, 1);
    // 7. vocab input gates
    gemm_mma<<<dim3(32, 8), 256, GM_TOT>>>(p_bbf, p_wihd, dec_bih, dec_bhh,
                                           p_vxg, nullptr, VSZ, G4, 0);
    // 8. step-0 input gates from sos
    gemm_mma<<<dim3(32, 8), 256, GM_TOT>>>(p_sosbf, p_wihd, dec_bih, dec_bhh,
                                           p_dxg0, nullptr, SB, G4, 0);
    // 9-18. decoder: 5 sequential steps
    for (int t = 0; t <= LSEG; t++) {
        gemm_mma<<<dim3(32, 8), 256, GM_TOT>>>(p_dhbf, p_whhd, nullptr, nullptr,
                                               p_gates, nullptr, SB, G4, 2);
        dec_point<<<SB/4, 1024>>>(p_gates, p_dxg0, p_vxg, x, dec_bih, dec_bhh,
                                  p_dec_c, p_dhbf, p_abf, t);
    }
    // 19. bf16 mma.sync logits + fused LSE/target/EOS
    logits_mma<<<MTILES, 256, SMTOT>>>(p_abf, p_bbf, e2vb, x, p_lse, p_tgt, p_eos);
    // 20. segment log-probs table
    logpy_kernel<<<((SSEG+1)*BSZ + 127)/128, 128>>>(p_lse, p_tgt, p_eos, p_issing, p_logpy);
    // 21. DP + reduction -> scalar
    dp_kernel<<<1, 32>>>(p_logpy, lengths, out);

    (void)in_sizes; (void)n_in; (void)out_size;
}